// round 15
// baseline (speedup 1.0000x reference)
#include <cuda_runtime.h>
#include <cuda_fp16.h>
#include <cstdint>

// EnsembleRBF via mma.sync m16n8k16 fp16 (A fp16, B fp16, fp32 accum).
// out[m,n,d] = sum_c exp(-||x_n-c||^2) * sigma^2 * W[m,c,d]
// N=100000, C=256, D=2, M=5.
// R15: grid 782 (1 tile/block, TPB 256, C-split x2) + __launch_bounds__(256,4)
// forcing <=64 regs -> 4 resident blocks (32 warps/SM) for latency coverage.
// Simple float4 staging (R14's, cheapest measured).

#define TPB 256
#define PTS_PER_BLOCK 128
#define C_CENTERS 256
#define HSTEPS 8
#define NSTEPS 16
#define CB_ST 130

__device__ __forceinline__ float ex2a(float v) {
    float r; asm("ex2.approx.ftz.f32 %0, %1;" : "=f"(r) : "f"(v)); return r;
}
// pack {upper=a, lower=b} as f16x2
__device__ __forceinline__ uint32_t hpack(float a, float b) {
    uint32_t d;
    asm("cvt.rn.f16x2.f32 %0, %1, %2;" : "=r"(d) : "f"(a), "f"(b));
    return d;
}

__device__ __forceinline__ void mma16816(float* c,
    uint32_t a0, uint32_t a1, uint32_t a2, uint32_t a3, uint32_t b0, uint32_t b1) {
    asm volatile(
        "mma.sync.aligned.m16n8k16.row.col.f32.f16.f16.f32 "
        "{%0,%1,%2,%3}, {%4,%5,%6,%7}, {%8,%9}, {%0,%1,%2,%3};"
        : "+f"(c[0]), "+f"(c[1]), "+f"(c[2]), "+f"(c[3])
        : "r"(a0), "r"(a1), "r"(a2), "r"(a3), "r"(b0), "r"(b1));
}

__global__ void __launch_bounds__(TPB, 4)
rbf_mma_kernel(const float* __restrict__ x,
               const float* __restrict__ centers,
               const float* __restrict__ weights,
               float* __restrict__ out,
               int n) {
    // gtab[c] = (2*L2E*cx, 2*L2E*cy, -L2E*|c|^2, 0)
    __shared__ float4 gtab[C_CENTERS];                 // 4KB
    // B fragments [step][lane] -> uint4 {t0b0, t0b1, t1b0, t1b1} (fp16)
    __shared__ uint4 bfragH[NSTEPS * 32];              // 8KB
    __shared__ float cbuf[16 * CB_ST];                 // 8.1KB transpose + reduce

    const int tid = threadIdx.x;
    const int lane = tid & 31;
    const int w = tid >> 5;
    const int wq = w & 3;        // point-group within block
    const int chalf = w >> 2;    // which half of centers
    const float L2E = 1.4426950408889634f;

    // ---- stage gtab ----
    for (int c = tid; c < C_CENTERS; c += TPB) {
        const float2 cc = reinterpret_cast<const float2*>(centers)[c];
        gtab[c] = make_float4(2.0f * L2E * cc.x, 2.0f * L2E * cc.y,
                              -L2E * (cc.x * cc.x + cc.y * cc.y), 0.0f);
    }
    // ---- stage B fragments (float4 loads; cols >= 10 zero) ----
    for (int e = tid; e < NSTEPS * 32; e += TPB) {
        const int s = e >> 5;
        const int l = e & 31;
        uint32_t hh[4];
#pragma unroll
        for (int t = 0; t < 2; t++) {
#pragma unroll
            for (int b = 0; b < 2; b++) {
                const int j = t * 8 + (l >> 2);              // output column (2m+d)
                const int k = s * 16 + (l & 3) * 2 + b * 8;  // center index
                float w0 = 0.0f, w1 = 0.0f;
                if (j < 10) {
                    // one float4 = {W[m,k,0],W[m,k,1],W[m,k+1,0],W[m,k+1,1]}
                    const float4 F = *reinterpret_cast<const float4*>(
                        weights + (j >> 1) * 512 + k * 2);
                    w0 = (j & 1) ? F.y : F.x;
                    w1 = (j & 1) ? F.w : F.z;
                }
                hh[t * 2 + b] = hpack(w1, w0);   // {upper=k+1, lower=k}
            }
        }
        bfragH[e] = make_uint4(hh[0], hh[1], hh[2], hh[3]);
    }
    __syncthreads();

    const int kb = (lane & 3) * 2;
    const int lp = wq * 32 + (lane >> 2);
    const int j0 = (lane & 3) * 2;
    const int gbase = blockIdx.x * PTS_PER_BLOCK;

    // ---- 4 points per lane: tile A rows (lp, lp+8), tile B rows (+16, +24)
    const int q0 = gbase + lp;
    const float2 XA0 = reinterpret_cast<const float2*>(x)[q0 < n ? q0 : (n - 1)];
    const float2 XA1 = reinterpret_cast<const float2*>(x)[(q0 + 8) < n ? (q0 + 8) : (n - 1)];
    const float2 XB0 = reinterpret_cast<const float2*>(x)[(q0 + 16) < n ? (q0 + 16) : (n - 1)];
    const float2 XB1 = reinterpret_cast<const float2*>(x)[(q0 + 24) < n ? (q0 + 24) : (n - 1)];
    // per-point bias: -L2E*|x|^2 - 4  (sigma^2 = 2^-4 folded)
    const float tA0 = fmaf(fmaf(XA0.x, XA0.x, XA0.y * XA0.y), -L2E, -4.0f);
    const float tA1 = fmaf(fmaf(XA1.x, XA1.x, XA1.y * XA1.y), -L2E, -4.0f);
    const float tB0 = fmaf(fmaf(XB0.x, XB0.x, XB0.y * XB0.y), -L2E, -4.0f);
    const float tB1 = fmaf(fmaf(XB1.x, XB1.x, XB1.y * XB1.y), -L2E, -4.0f);

    float cA0[4] = {0.f, 0.f, 0.f, 0.f};  // tile A, cols 0-7
    float cA1[4] = {0.f, 0.f, 0.f, 0.f};  // tile A, cols 8-15
    float cB0[4] = {0.f, 0.f, 0.f, 0.f};  // tile B, cols 0-7
    float cB1[4] = {0.f, 0.f, 0.f, 0.f};  // tile B, cols 8-15

#pragma unroll
    for (int k = 0; k < HSTEPS; k++) {
        const int s = chalf * HSTEPS + k;
        const float4* gp = &gtab[s * 16 + kb];
        const float4 g0 = gp[0], g1 = gp[1], g2 = gp[8], g3 = gp[9];

        const float rA00 = ex2a(fmaf(XA0.x, g0.x, fmaf(XA0.y, g0.y, g0.z)) + tA0);
        const float rA01 = ex2a(fmaf(XA0.x, g1.x, fmaf(XA0.y, g1.y, g1.z)) + tA0);
        const float rA02 = ex2a(fmaf(XA0.x, g2.x, fmaf(XA0.y, g2.y, g2.z)) + tA0);
        const float rA03 = ex2a(fmaf(XA0.x, g3.x, fmaf(XA0.y, g3.y, g3.z)) + tA0);
        const float rA10 = ex2a(fmaf(XA1.x, g0.x, fmaf(XA1.y, g0.y, g0.z)) + tA1);
        const float rA11 = ex2a(fmaf(XA1.x, g1.x, fmaf(XA1.y, g1.y, g1.z)) + tA1);
        const float rA12 = ex2a(fmaf(XA1.x, g2.x, fmaf(XA1.y, g2.y, g2.z)) + tA1);
        const float rA13 = ex2a(fmaf(XA1.x, g3.x, fmaf(XA1.y, g3.y, g3.z)) + tA1);
        const float rB00 = ex2a(fmaf(XB0.x, g0.x, fmaf(XB0.y, g0.y, g0.z)) + tB0);
        const float rB01 = ex2a(fmaf(XB0.x, g1.x, fmaf(XB0.y, g1.y, g1.z)) + tB0);
        const float rB02 = ex2a(fmaf(XB0.x, g2.x, fmaf(XB0.y, g2.y, g2.z)) + tB0);
        const float rB03 = ex2a(fmaf(XB0.x, g3.x, fmaf(XB0.y, g3.y, g3.z)) + tB0);
        const float rB10 = ex2a(fmaf(XB1.x, g0.x, fmaf(XB1.y, g0.y, g0.z)) + tB1);
        const float rB11 = ex2a(fmaf(XB1.x, g1.x, fmaf(XB1.y, g1.y, g1.z)) + tB1);
        const float rB12 = ex2a(fmaf(XB1.x, g2.x, fmaf(XB1.y, g2.y, g2.z)) + tB1);
        const float rB13 = ex2a(fmaf(XB1.x, g3.x, fmaf(XB1.y, g3.y, g3.z)) + tB1);

        // A fragments: {upper = k+1 col, lower = k col}
        const uint32_t aA0 = hpack(rA01, rA00);
        const uint32_t aA1 = hpack(rA11, rA10);
        const uint32_t aA2 = hpack(rA03, rA02);
        const uint32_t aA3 = hpack(rA13, rA12);
        const uint32_t aB0 = hpack(rB01, rB00);
        const uint32_t aB1 = hpack(rB11, rB10);
        const uint32_t aB2 = hpack(rB03, rB02);
        const uint32_t aB3 = hpack(rB13, rB12);

        const uint4 BH = bfragH[s * 32 + lane];

        mma16816(cA0, aA0, aA1, aA2, aA3, BH.x, BH.y);
        mma16816(cA1, aA0, aA1, aA2, aA3, BH.z, BH.w);
        mma16816(cB0, aB0, aB1, aB2, aB3, BH.x, BH.y);
        mma16816(cB1, aB0, aB1, aB2, aB3, BH.z, BH.w);
    }

    // ---- epilogue: merge C-halves in the transpose buffer ----
    const int pA0 = lp, pA1 = lp + 8, pB0 = lp + 16, pB1 = lp + 24;

    if (chalf == 0) {
        cbuf[(j0 + 0) * CB_ST + pA0] = cA0[0];
        cbuf[(j0 + 1) * CB_ST + pA0] = cA0[1];
        cbuf[(j0 + 0) * CB_ST + pA1] = cA0[2];
        cbuf[(j0 + 1) * CB_ST + pA1] = cA0[3];
        cbuf[(j0 + 8) * CB_ST + pA0] = cA1[0];
        cbuf[(j0 + 9) * CB_ST + pA0] = cA1[1];
        cbuf[(j0 + 8) * CB_ST + pA1] = cA1[2];
        cbuf[(j0 + 9) * CB_ST + pA1] = cA1[3];
        cbuf[(j0 + 0) * CB_ST + pB0] = cB0[0];
        cbuf[(j0 + 1) * CB_ST + pB0] = cB0[1];
        cbuf[(j0 + 0) * CB_ST + pB1] = cB0[2];
        cbuf[(j0 + 1) * CB_ST + pB1] = cB0[3];
        cbuf[(j0 + 8) * CB_ST + pB0] = cB1[0];
        cbuf[(j0 + 9) * CB_ST + pB0] = cB1[1];
        cbuf[(j0 + 8) * CB_ST + pB1] = cB1[2];
        cbuf[(j0 + 9) * CB_ST + pB1] = cB1[3];
    }
    __syncthreads();
    if (chalf == 1) {
        cbuf[(j0 + 0) * CB_ST + pA0] += cA0[0];
        cbuf[(j0 + 1) * CB_ST + pA0] += cA0[1];
        cbuf[(j0 + 0) * CB_ST + pA1] += cA0[2];
        cbuf[(j0 + 1) * CB_ST + pA1] += cA0[3];
        cbuf[(j0 + 8) * CB_ST + pA0] += cA1[0];
        cbuf[(j0 + 9) * CB_ST + pA0] += cA1[1];
        cbuf[(j0 + 8) * CB_ST + pA1] += cA1[2];
        cbuf[(j0 + 9) * CB_ST + pA1] += cA1[3];
        cbuf[(j0 + 0) * CB_ST + pB0] += cB0[0];
        cbuf[(j0 + 1) * CB_ST + pB0] += cB0[1];
        cbuf[(j0 + 0) * CB_ST + pB1] += cB0[2];
        cbuf[(j0 + 1) * CB_ST + pB1] += cB0[3];
        cbuf[(j0 + 8) * CB_ST + pB0] += cB1[0];
        cbuf[(j0 + 9) * CB_ST + pB0] += cB1[1];
        cbuf[(j0 + 8) * CB_ST + pB1] += cB1[2];
        cbuf[(j0 + 9) * CB_ST + pB1] += cB1[3];
    }
    __syncthreads();

    for (int e = tid; e < 5 * PTS_PER_BLOCK; e += TPB) {
        const int m = e >> 7;      // 0..4
        const int p = e & 127;
        const int gp = gbase + p;
        if (gp < n) {
            const float2 v = make_float2(cbuf[(2 * m + 0) * CB_ST + p],
                                         cbuf[(2 * m + 1) * CB_ST + p]);
            *reinterpret_cast<float2*>(out + (size_t)m * n * 2 + (size_t)gp * 2) = v;
        }
    }
}

extern "C" void kernel_launch(void* const* d_in, const int* in_sizes, int n_in,
                              void* d_out, int out_size) {
    const float* x = (const float*)d_in[0];        // [N, 2]
    const float* centers = (const float*)d_in[1];  // [256, 2]
    const float* weights = (const float*)d_in[2];  // [5, 256, 2]
    float* out = (float*)d_out;                    // [5, N, 2]

    const int n = in_sizes[0] / 2;
    const int blocks = (n + PTS_PER_BLOCK - 1) / PTS_PER_BLOCK;
    rbf_mma_kernel<<<blocks, TPB>>>(x, centers, weights, out, n);
}

// round 16
// speedup vs baseline: 1.0198x; 1.0198x over previous
#include <cuda_runtime.h>
#include <cuda_fp16.h>
#include <cstdint>

// EnsembleRBF via mma.sync m16n8k16 fp16 (A fp16, B fp16, fp32 accum).
// out[m,n,d] = sum_c exp(-||x_n-c||^2) * sigma^2 * W[m,c,d]
// N=100000, C=256, D=2, M=5.
// R16: R11 two-kernel split (prep builds B-fragment table in global; main is
// the measured-11.9us pure mainloop) + Programmatic Dependent Launch to hide
// the prep->main serialization gap that cost R11 its win.

#define TPB 256
#define PTS_PER_BLOCK 128
#define C_CENTERS 256
#define HSTEPS 8
#define NSTEPS 16
#define CB_ST 130

// One-time B fragment table: [step][lane] -> uint4 {n0b0, n0b1, n1b0, n1b1}
__device__ uint4 bfrag_g[NSTEPS * 32];

__device__ __forceinline__ float ex2a(float v) {
    float r; asm("ex2.approx.ftz.f32 %0, %1;" : "=f"(r) : "f"(v)); return r;
}
// pack {upper=a, lower=b} as f16x2
__device__ __forceinline__ uint32_t hpack(float a, float b) {
    uint32_t d;
    asm("cvt.rn.f16x2.f32 %0, %1, %2;" : "=r"(d) : "f"(a), "f"(b));
    return d;
}
__device__ __forceinline__ void gdc_launch_dependents() {
    asm volatile("griddepcontrol.launch_dependents;");
}
__device__ __forceinline__ void gdc_wait() {
    asm volatile("griddepcontrol.wait;" ::: "memory");
}

__device__ __forceinline__ void mma16816(float* c,
    uint32_t a0, uint32_t a1, uint32_t a2, uint32_t a3, uint32_t b0, uint32_t b1) {
    asm volatile(
        "mma.sync.aligned.m16n8k16.row.col.f32.f16.f16.f32 "
        "{%0,%1,%2,%3}, {%4,%5,%6,%7}, {%8,%9}, {%0,%1,%2,%3};"
        : "+f"(c[0]), "+f"(c[1]), "+f"(c[2]), "+f"(c[3])
        : "r"(a0), "r"(a1), "r"(a2), "r"(a3), "r"(b0), "r"(b1));
}

// ---- prep: build B fragments once, then release dependents ----
__global__ void prep_kernel(const float* __restrict__ weights) {
    const int e = blockIdx.x * 128 + threadIdx.x;
    if (e < NSTEPS * 32) {
        const int s = e >> 5;
        const int l = e & 31;
        uint32_t hh[4];
#pragma unroll
        for (int t = 0; t < 2; t++) {
#pragma unroll
            for (int b = 0; b < 2; b++) {
                const int j = t * 8 + (l >> 2);              // output column (2m+d)
                const int k = s * 16 + (l & 3) * 2 + b * 8;  // center index
                float w0 = 0.0f, w1 = 0.0f;
                if (j < 10) {
                    const float4 F = *reinterpret_cast<const float4*>(
                        weights + (j >> 1) * 512 + k * 2);
                    w0 = (j & 1) ? F.y : F.x;
                    w1 = (j & 1) ? F.w : F.z;
                }
                hh[t * 2 + b] = hpack(w1, w0);   // {upper=k+1, lower=k}
            }
        }
        bfrag_g[e] = make_uint4(hh[0], hh[1], hh[2], hh[3]);
    }
    __syncthreads();                  // all writes of this CTA done
    gdc_launch_dependents();          // release the main kernel
}

__global__ void __launch_bounds__(TPB)
rbf_mma_kernel(const float* __restrict__ x,
               const float* __restrict__ centers,
               float* __restrict__ out,
               int n) {
    // gtab[c] = (2*L2E*cx, 2*L2E*cy, -L2E*|c|^2, 0)
    __shared__ float4 gtab[C_CENTERS];                 // 4KB
    __shared__ float cbuf[16 * CB_ST];                 // 8.1KB transpose + reduce

    const int tid = threadIdx.x;
    const int lane = tid & 31;
    const int w = tid >> 5;
    const int wq = w & 3;        // point-group within block
    const int chalf = w >> 2;    // which half of centers
    const float L2E = 1.4426950408889634f;

    // ---- prep-independent preamble (runs while prep finishes) ----
    for (int c = tid; c < C_CENTERS; c += TPB) {
        const float2 cc = reinterpret_cast<const float2*>(centers)[c];
        gtab[c] = make_float4(2.0f * L2E * cc.x, 2.0f * L2E * cc.y,
                              -L2E * (cc.x * cc.x + cc.y * cc.y), 0.0f);
    }

    const int gbase = blockIdx.x * PTS_PER_BLOCK;
    const int lp = wq * 32 + (lane >> 2);
    const int q0 = gbase + lp;
    const float2 XA0 = reinterpret_cast<const float2*>(x)[q0 < n ? q0 : (n - 1)];
    const float2 XA1 = reinterpret_cast<const float2*>(x)[(q0 + 8) < n ? (q0 + 8) : (n - 1)];
    const float2 XB0 = reinterpret_cast<const float2*>(x)[(q0 + 16) < n ? (q0 + 16) : (n - 1)];
    const float2 XB1 = reinterpret_cast<const float2*>(x)[(q0 + 24) < n ? (q0 + 24) : (n - 1)];
    // per-point bias: -L2E*|x|^2 - 4  (sigma^2 = 2^-4 folded)
    const float tA0 = fmaf(fmaf(XA0.x, XA0.x, XA0.y * XA0.y), -L2E, -4.0f);
    const float tA1 = fmaf(fmaf(XA1.x, XA1.x, XA1.y * XA1.y), -L2E, -4.0f);
    const float tB0 = fmaf(fmaf(XB0.x, XB0.x, XB0.y * XB0.y), -L2E, -4.0f);
    const float tB1 = fmaf(fmaf(XB1.x, XB1.x, XB1.y * XB1.y), -L2E, -4.0f);

    // ---- wait for prep's table, then sync the gtab staging ----
    gdc_wait();
    __syncthreads();

    const int kb = (lane & 3) * 2;

    float cA0[4] = {0.f, 0.f, 0.f, 0.f};  // tile A, cols 0-7
    float cA1[4] = {0.f, 0.f, 0.f, 0.f};  // tile A, cols 8-15
    float cB0[4] = {0.f, 0.f, 0.f, 0.f};  // tile B, cols 0-7
    float cB1[4] = {0.f, 0.f, 0.f, 0.f};  // tile B, cols 8-15

#pragma unroll
    for (int k = 0; k < HSTEPS; k++) {
        const int s = chalf * HSTEPS + k;
        const float4* gp = &gtab[s * 16 + kb];
        const float4 g0 = gp[0], g1 = gp[1], g2 = gp[8], g3 = gp[9];

        const float rA00 = ex2a(fmaf(XA0.x, g0.x, fmaf(XA0.y, g0.y, g0.z)) + tA0);
        const float rA01 = ex2a(fmaf(XA0.x, g1.x, fmaf(XA0.y, g1.y, g1.z)) + tA0);
        const float rA02 = ex2a(fmaf(XA0.x, g2.x, fmaf(XA0.y, g2.y, g2.z)) + tA0);
        const float rA03 = ex2a(fmaf(XA0.x, g3.x, fmaf(XA0.y, g3.y, g3.z)) + tA0);
        const float rA10 = ex2a(fmaf(XA1.x, g0.x, fmaf(XA1.y, g0.y, g0.z)) + tA1);
        const float rA11 = ex2a(fmaf(XA1.x, g1.x, fmaf(XA1.y, g1.y, g1.z)) + tA1);
        const float rA12 = ex2a(fmaf(XA1.x, g2.x, fmaf(XA1.y, g2.y, g2.z)) + tA1);
        const float rA13 = ex2a(fmaf(XA1.x, g3.x, fmaf(XA1.y, g3.y, g3.z)) + tA1);
        const float rB00 = ex2a(fmaf(XB0.x, g0.x, fmaf(XB0.y, g0.y, g0.z)) + tB0);
        const float rB01 = ex2a(fmaf(XB0.x, g1.x, fmaf(XB0.y, g1.y, g1.z)) + tB0);
        const float rB02 = ex2a(fmaf(XB0.x, g2.x, fmaf(XB0.y, g2.y, g2.z)) + tB0);
        const float rB03 = ex2a(fmaf(XB0.x, g3.x, fmaf(XB0.y, g3.y, g3.z)) + tB0);
        const float rB10 = ex2a(fmaf(XB1.x, g0.x, fmaf(XB1.y, g0.y, g0.z)) + tB1);
        const float rB11 = ex2a(fmaf(XB1.x, g1.x, fmaf(XB1.y, g1.y, g1.z)) + tB1);
        const float rB12 = ex2a(fmaf(XB1.x, g2.x, fmaf(XB1.y, g2.y, g2.z)) + tB1);
        const float rB13 = ex2a(fmaf(XB1.x, g3.x, fmaf(XB1.y, g3.y, g3.z)) + tB1);

        // A fragments: {upper = k+1 col, lower = k col}
        const uint32_t aA0 = hpack(rA01, rA00);
        const uint32_t aA1 = hpack(rA11, rA10);
        const uint32_t aA2 = hpack(rA03, rA02);
        const uint32_t aA3 = hpack(rA13, rA12);
        const uint32_t aB0 = hpack(rB01, rB00);
        const uint32_t aB1 = hpack(rB11, rB10);
        const uint32_t aB2 = hpack(rB03, rB02);
        const uint32_t aB3 = hpack(rB13, rB12);

        const uint4 BH = __ldg(&bfrag_g[s * 32 + lane]);

        mma16816(cA0, aA0, aA1, aA2, aA3, BH.x, BH.y);
        mma16816(cA1, aA0, aA1, aA2, aA3, BH.z, BH.w);
        mma16816(cB0, aB0, aB1, aB2, aB3, BH.x, BH.y);
        mma16816(cB1, aB0, aB1, aB2, aB3, BH.z, BH.w);
    }

    // ---- epilogue: merge C-halves in the transpose buffer ----
    const int j0 = (lane & 3) * 2;
    const int pA0 = lp, pA1 = lp + 8, pB0 = lp + 16, pB1 = lp + 24;

    if (chalf == 0) {
        cbuf[(j0 + 0) * CB_ST + pA0] = cA0[0];
        cbuf[(j0 + 1) * CB_ST + pA0] = cA0[1];
        cbuf[(j0 + 0) * CB_ST + pA1] = cA0[2];
        cbuf[(j0 + 1) * CB_ST + pA1] = cA0[3];
        cbuf[(j0 + 8) * CB_ST + pA0] = cA1[0];
        cbuf[(j0 + 9) * CB_ST + pA0] = cA1[1];
        cbuf[(j0 + 8) * CB_ST + pA1] = cA1[2];
        cbuf[(j0 + 9) * CB_ST + pA1] = cA1[3];
        cbuf[(j0 + 0) * CB_ST + pB0] = cB0[0];
        cbuf[(j0 + 1) * CB_ST + pB0] = cB0[1];
        cbuf[(j0 + 0) * CB_ST + pB1] = cB0[2];
        cbuf[(j0 + 1) * CB_ST + pB1] = cB0[3];
        cbuf[(j0 + 8) * CB_ST + pB0] = cB1[0];
        cbuf[(j0 + 9) * CB_ST + pB0] = cB1[1];
        cbuf[(j0 + 8) * CB_ST + pB1] = cB1[2];
        cbuf[(j0 + 9) * CB_ST + pB1] = cB1[3];
    }
    __syncthreads();
    if (chalf == 1) {
        cbuf[(j0 + 0) * CB_ST + pA0] += cA0[0];
        cbuf[(j0 + 1) * CB_ST + pA0] += cA0[1];
        cbuf[(j0 + 0) * CB_ST + pA1] += cA0[2];
        cbuf[(j0 + 1) * CB_ST + pA1] += cA0[3];
        cbuf[(j0 + 8) * CB_ST + pA0] += cA1[0];
        cbuf[(j0 + 9) * CB_ST + pA0] += cA1[1];
        cbuf[(j0 + 8) * CB_ST + pA1] += cA1[2];
        cbuf[(j0 + 9) * CB_ST + pA1] += cA1[3];
        cbuf[(j0 + 0) * CB_ST + pB0] += cB0[0];
        cbuf[(j0 + 1) * CB_ST + pB0] += cB0[1];
        cbuf[(j0 + 0) * CB_ST + pB1] += cB0[2];
        cbuf[(j0 + 1) * CB_ST + pB1] += cB0[3];
        cbuf[(j0 + 8) * CB_ST + pB0] += cB1[0];
        cbuf[(j0 + 9) * CB_ST + pB0] += cB1[1];
        cbuf[(j0 + 8) * CB_ST + pB1] += cB1[2];
        cbuf[(j0 + 9) * CB_ST + pB1] += cB1[3];
    }
    __syncthreads();

    for (int e = tid; e < 5 * PTS_PER_BLOCK; e += TPB) {
        const int m = e >> 7;      // 0..4
        const int p = e & 127;
        const int gp = gbase + p;
        if (gp < n) {
            const float2 v = make_float2(cbuf[(2 * m + 0) * CB_ST + p],
                                         cbuf[(2 * m + 1) * CB_ST + p]);
            *reinterpret_cast<float2*>(out + (size_t)m * n * 2 + (size_t)gp * 2) = v;
        }
    }
}

extern "C" void kernel_launch(void* const* d_in, const int* in_sizes, int n_in,
                              void* d_out, int out_size) {
    const float* x = (const float*)d_in[0];        // [N, 2]
    const float* centers = (const float*)d_in[1];  // [256, 2]
    const float* weights = (const float*)d_in[2];  // [5, 256, 2]
    float* out = (float*)d_out;                    // [5, N, 2]

    const int n = in_sizes[0] / 2;

    prep_kernel<<<4, 128>>>(weights);

    // Main kernel with Programmatic Dependent Launch: may launch while prep
    // is still running; gdc_wait() inside guarantees table visibility.
    const int blocks = (n + PTS_PER_BLOCK - 1) / PTS_PER_BLOCK;
    cudaLaunchConfig_t cfg = {};
    cfg.gridDim = dim3(blocks, 1, 1);
    cfg.blockDim = dim3(TPB, 1, 1);
    cfg.dynamicSmemBytes = 0;
    cfg.stream = 0;
    cudaLaunchAttribute attrs[1];
    attrs[0].id = cudaLaunchAttributeProgrammaticStreamSerialization;
    attrs[0].val.programmaticStreamSerializationAllowed = 1;
    cfg.attrs = attrs;
    cfg.numAttrs = 1;
    cudaLaunchKernelEx(&cfg, rbf_mma_kernel, x, centers, out, n);
}